// round 14
// baseline (speedup 1.0000x reference)
#include <cuda_runtime.h>
#include <cuda_bf16.h>
#include <cuda_fp16.h>
#include <cstdint>

#define MAXN 100000
#define MAXE 1600000
#define C 128
#define NBMAX 1024
#define KP 136   // padded K row length (bf16): 272B rows -> conflict-free ldmatrix
#define GEMM_GRID 148

// ================= static scratch =================
__device__ int   g_cnt[MAXN];
__device__ int   g_rowptr[MAXN + 1];
__device__ float g_dinv[MAXN];
__device__ int   g_srcs[MAXE];
__device__ int   g_rank[MAXE];
__device__ int   g_blocksum[NBMAX];
__device__ int   g_blockoff[NBMAX];
__device__ __half g_xh[(size_t)MAXN * C];   // dinv-scaled x in fp16
__device__ __half g_h [(size_t)MAXN * C];   // dinv*relu(layer1) in fp16
__device__ __half g_ax[(size_t)MAXN * C];   // agg(x) fp16
__device__ __half g_ah[(size_t)MAXN * C];   // agg(h) fp16
__device__ __nv_bfloat16 g_w1hi[C * C], g_w1lo[C * C];  // W1^T  [n][k] bf16 hi/lo
__device__ __nv_bfloat16 g_w2hi[C * C], g_w2lo[C * C];  // [Wmu|Wls]^T
__device__ float g_b2[C];

// ================= helpers =================
__device__ __forceinline__ uint32_t smem_u32(const void* p) {
    uint32_t a;
    asm("{ .reg .u64 t; cvta.to.shared.u64 t, %1; cvt.u32.u64 %0, t; }" : "=r"(a) : "l"(p));
    return a;
}
__device__ __forceinline__ void ldsm_x4(uint32_t* r, uint32_t addr) {
    asm volatile("ldmatrix.sync.aligned.m8n8.x4.shared.b16 {%0,%1,%2,%3}, [%4];"
        : "=r"(r[0]), "=r"(r[1]), "=r"(r[2]), "=r"(r[3]) : "r"(addr));
}
__device__ __forceinline__ void mma16816(float* d, const uint32_t* a, const uint32_t* b) {
    asm volatile("mma.sync.aligned.m16n8k16.row.col.f32.bf16.bf16.f32 "
        "{%0,%1,%2,%3}, {%4,%5,%6,%7}, {%8,%9}, {%0,%1,%2,%3};"
        : "+f"(d[0]), "+f"(d[1]), "+f"(d[2]), "+f"(d[3])
        : "r"(a[0]), "r"(a[1]), "r"(a[2]), "r"(a[3]), "r"(b[0]), "r"(b[1]));
}
__device__ __forceinline__ uint32_t pack_bf2(float a, float b) {
    __nv_bfloat162 t = __halves2bfloat162(__float2bfloat16_rn(a), __float2bfloat16_rn(b));
    return *reinterpret_cast<uint32_t*>(&t);
}
// accumulate 8 fp16 (uint4) into 8 fp32
__device__ __forceinline__ void addh8(float* acc, uint4 v) {
    const __half2* hp = (const __half2*)&v;
#pragma unroll
    for (int q = 0; q < 4; q++) {
        float2 f = __half22float2(hp[q]);
        acc[q * 2 + 0] += f.x;
        acc[q * 2 + 1] += f.y;
    }
}

// ================= CSR build =================
__global__ void init_pack_kernel(int n, int nb_n,
                                 const float* __restrict__ W1,
                                 const float* __restrict__ Wmu, const float* __restrict__ bmu,
                                 const float* __restrict__ Wls, const float* __restrict__ bls) {
    if ((int)blockIdx.x < nb_n) {
        int i = blockIdx.x * blockDim.x + threadIdx.x;
        if (i < n) g_cnt[i] = 0;
    } else {
        int pb = blockIdx.x - nb_n;          // 0..255
        int k = pb & 127;
        int layer = pb >> 7;
        int nn = threadIdx.x;
        if (nn < 128) {
            float w;
            if (layer == 0) w = W1[k * 128 + nn];
            else            w = (nn < 64) ? Wmu[k * 64 + nn] : Wls[k * 64 + (nn - 64)];
            __nv_bfloat16 bh = __float2bfloat16_rn(w);
            __nv_bfloat16 bl = __float2bfloat16_rn(w - __bfloat162float(bh));
            if (layer == 0) { g_w1hi[nn * 128 + k] = bh; g_w1lo[nn * 128 + k] = bl; }
            else {
                g_w2hi[nn * 128 + k] = bh; g_w2lo[nn * 128 + k] = bl;
                if (k == 0) g_b2[nn] = (nn < 64) ? bmu[nn] : bls[nn - 64];
            }
        }
    }
}
// count + record per-edge rank; 4 edges per thread (int4)
__global__ void count_kernel(const int* __restrict__ col, int e) {
    int i4 = blockIdx.x * blockDim.x + threadIdx.x;
    int base = i4 * 4;
    if (base + 4 <= e) {
        int4 c = ((const int4*)col)[i4];
        int r0 = atomicAdd(&g_cnt[c.x], 1);
        int r1 = atomicAdd(&g_cnt[c.y], 1);
        int r2 = atomicAdd(&g_cnt[c.z], 1);
        int r3 = atomicAdd(&g_cnt[c.w], 1);
        ((int4*)g_rank)[i4] = make_int4(r0, r1, r2, r3);
    } else {
        for (int i = base; i < e; i++) g_rank[i] = atomicAdd(&g_cnt[col[i]], 1);
    }
}
__global__ void scanA_kernel(int n) {
    __shared__ int red[256];
    int i = blockIdx.x * 256 + threadIdx.x;
    red[threadIdx.x] = (i < n) ? g_cnt[i] : 0;
    __syncthreads();
    for (int off = 128; off > 0; off >>= 1) {
        if (threadIdx.x < off) red[threadIdx.x] += red[threadIdx.x + off];
        __syncthreads();
    }
    if (threadIdx.x == 0) g_blocksum[blockIdx.x] = red[0];
}
__global__ void scanB_kernel(int nb, int n) {
    __shared__ int s[NBMAX];
    int t = threadIdx.x;
    int v = (t < nb) ? g_blocksum[t] : 0;
    s[t] = v;
    __syncthreads();
    for (int off = 1; off < NBMAX; off <<= 1) {
        int u = (t >= off) ? s[t - off] : 0;
        __syncthreads();
        s[t] += u;
        __syncthreads();
    }
    if (t < nb) g_blockoff[t] = s[t] - v;
    if (t == NBMAX - 1) g_rowptr[n] = s[NBMAX - 1];
}
// scan + dinv + fused x->fp16 pre-scale
__global__ void scanC_kernel(const float* __restrict__ x, int n) {
    __shared__ int s[256];
    __shared__ float sd[256];
    int i = blockIdx.x * 256 + threadIdx.x;
    int c = (i < n) ? g_cnt[i] : 0;
    s[threadIdx.x] = c;
    __syncthreads();
    for (int off = 1; off < 256; off <<= 1) {
        int u = (threadIdx.x >= off) ? s[threadIdx.x - off] : 0;
        __syncthreads();
        s[threadIdx.x] += u;
        __syncthreads();
    }
    float d = rsqrtf((float)(c + 1));
    if (i < n) {
        g_rowptr[i] = g_blockoff[blockIdx.x] + s[threadIdx.x] - c;
        g_dinv[i]   = d;
    }
    sd[threadIdx.x] = d;
    __syncthreads();

    size_t base = (size_t)blockIdx.x * 256;
    int lim = n - (int)base; if (lim > 256) lim = 256;
    if (lim <= 0) return;
    for (int j = threadIdx.x; j < lim * 32; j += 256) {
        int local = j >> 5;
        float dv = sd[local];
        float4 v = ((const float4*)x)[(base + local) * 32 + (j & 31)];
        __half2 a = __floats2half2_rn(v.x * dv, v.y * dv);
        __half2 b = __floats2half2_rn(v.z * dv, v.w * dv);
        ((uint2*)g_xh)[(base + local) * 32 + (j & 31)] =
            make_uint2(*reinterpret_cast<uint32_t*>(&a), *reinterpret_cast<uint32_t*>(&b));
    }
}
// atomic-free scatter; 4 edges per thread (int4)
__global__ void scatter_kernel(const int* __restrict__ row, const int* __restrict__ col, int e) {
    int i4 = blockIdx.x * blockDim.x + threadIdx.x;
    int base = i4 * 4;
    if (base + 4 <= e) {
        int4 c = ((const int4*)col)[i4];
        int4 r = ((const int4*)row)[i4];
        int4 k = ((const int4*)g_rank)[i4];
        g_srcs[g_rowptr[c.x] + k.x] = r.x;
        g_srcs[g_rowptr[c.y] + k.y] = r.y;
        g_srcs[g_rowptr[c.z] + k.z] = r.z;
        g_srcs[g_rowptr[c.w] + k.w] = r.w;
    } else {
        for (int i = base; i < e; i++)
            g_srcs[g_rowptr[col[i]] + g_rank[i]] = row[i];
    }
}

// ================= aggregation: warp/node, paired-edge LDG.128 gather ==============
// Lanes 0-15 handle even edges, 16-31 odd edges; each lane loads uint4 = 8 fp16 ch.
// One warp LDG.128 fetches TWO edges' rows. Cross-half shfl_xor(16) reduction at end.
// PHASE 0: src = g_xh -> g_ax       PHASE 1: src = g_h -> g_ah
template <int PHASE>
__global__ void agg_kernel(int n) {
    int w = (blockIdx.x * blockDim.x + threadIdx.x) >> 5;
    int lane = threadIdx.x & 31;
    if (w >= n) return;
    const uint4* __restrict__ s4 = (PHASE == 0) ? (const uint4*)g_xh : (const uint4*)g_h;

    int g = lane & 15;        // channel group: covers ch [g*8, g*8+8)
    int side = lane >> 4;     // edge parity

    float acc[8];
#pragma unroll
    for (int q = 0; q < 8; q++) acc[q] = 0.f;

    int p = g_rowptr[w];
    int end = g_rowptr[w + 1];

    // batches of 8 edges: 4 LDG.128 per warp (2 edges each)
    for (; p + 8 <= end; p += 8) {
        int s_[8];
#pragma unroll
        for (int j = 0; j < 8; j++) s_[j] = g_srcs[p + j];
        uint4 v[4];
#pragma unroll
        for (int i = 0; i < 4; i++) v[i] = s4[(size_t)s_[2 * i + side] * 16 + g];
#pragma unroll
        for (int i = 0; i < 4; i++) addh8(acc, v[i]);
    }
    // pairs
    for (; p + 2 <= end; p += 2) {
        int s0 = g_srcs[p + side];
        addh8(acc, s4[(size_t)s0 * 16 + g]);
    }
    // final single edge (side 0 only)
    if (p < end && side == 0) {
        int s0 = g_srcs[p];
        addh8(acc, s4[(size_t)s0 * 16 + g]);
    }

    // reduce across warp halves
#pragma unroll
    for (int q = 0; q < 8; q++) acc[q] += __shfl_xor_sync(0xffffffffu, acc[q], 16);

    // epilogue: lanes 0-15 add self term, scale by dinv, store uint4 row
    if (side == 0) {
        float dw = g_dinv[w];
        addh8(acc, s4[(size_t)w * 16 + g]);   // self (pre-scaled)
#pragma unroll
        for (int q = 0; q < 8; q++) acc[q] *= dw;
        __half2 o0 = __floats2half2_rn(acc[0], acc[1]);
        __half2 o1 = __floats2half2_rn(acc[2], acc[3]);
        __half2 o2 = __floats2half2_rn(acc[4], acc[5]);
        __half2 o3 = __floats2half2_rn(acc[6], acc[7]);
        uint4* dst = (uint4*)((PHASE == 0) ? g_ax : g_ah);
        dst[(size_t)w * 16 + g] = make_uint4(*reinterpret_cast<uint32_t*>(&o0),
                                             *reinterpret_cast<uint32_t*>(&o1),
                                             *reinterpret_cast<uint32_t*>(&o2),
                                             *reinterpret_cast<uint32_t*>(&o3));
    }
}

// ================= persistent HMMA GEMM: B staged once, loop row tiles =============
// A read as fp16, split exactly into bf16 hi/lo during staging.
// MODE 0: A = g_ax, B = W1; epilogue g_h(fp16) = dinv*relu(D+b1)
// MODE 1: A = g_ah, B = W2; split -> mu / logstd (+g_b2)
template <int MODE>
__global__ void __launch_bounds__(256) mma_gemm_kernel(const float* __restrict__ bias1,
                                                       float* __restrict__ out0,
                                                       float* __restrict__ out1, int n) {
    extern __shared__ __align__(16) char smem[];
    __nv_bfloat16* sAh = (__nv_bfloat16*)smem;      // 128 x KP
    __nv_bfloat16* sAl = sAh + 128 * KP;
    __nv_bfloat16* sBh = sAl + 128 * KP;
    __nv_bfloat16* sBl = sBh + 128 * KP;
    int tid = threadIdx.x;
    int lane = tid & 31, wid = tid >> 5;

    // stage B once (persistent)
    {
        const uint4* gBh = (const uint4*)((MODE == 0) ? g_w1hi : g_w2hi);
        const uint4* gBl = (const uint4*)((MODE == 0) ? g_w1lo : g_w2lo);
        for (int i = tid; i < 128 * 16; i += 256) {
            int r = i >> 4, c = i & 15;
            *(uint4*)&sBh[r * KP + c * 8] = gBh[i];
            *(uint4*)&sBl[r * KP + c * 8] = gBl[i];
        }
    }

    const uint4* gA = (const uint4*)((MODE == 0) ? g_ax : g_ah);
    const float* bias = (MODE == 0) ? bias1 : g_b2;

    int wm = wid & 3;
    int wn = wid >> 2;
    uint32_t sbase = smem_u32(smem);
    int aRow  = wm * 32 + (lane & 15);
    int aKoff = (lane >> 4) << 3;
    int bRow  = wn * 64 + ((lane >> 4) << 3) + (lane & 7);
    int bKoff = ((lane >> 3) & 1) << 3;
    int quad = lane >> 2, tq = lane & 3;

    int ntiles = (n + 127) >> 7;
    for (int tile = blockIdx.x; tile < ntiles; tile += gridDim.x) {
        int row0 = tile << 7;
        __syncthreads();   // previous iteration's ldsm of sA complete
        for (int i = tid; i < 128 * 16; i += 256) {
            int r = i >> 4, c = i & 15;
            uint4 v = (row0 + r < n) ? gA[(size_t)(row0 + r) * 16 + c] : make_uint4(0, 0, 0, 0);
            // split 8 fp16 -> bf16 hi/lo (exact: fp16 mantissa fits in hi+lo)
            const __half2* hp = (const __half2*)&v;
            uint32_t hiw[4], low[4];
#pragma unroll
            for (int q = 0; q < 4; q++) {
                float2 f = __half22float2(hp[q]);
                __nv_bfloat16 bx = __float2bfloat16_rn(f.x);
                __nv_bfloat16 by = __float2bfloat16_rn(f.y);
                __nv_bfloat162 hv = __halves2bfloat162(bx, by);
                hiw[q] = *reinterpret_cast<uint32_t*>(&hv);
                low[q] = pack_bf2(f.x - __bfloat162float(bx), f.y - __bfloat162float(by));
            }
            *(uint4*)&sAh[r * KP + c * 8] = make_uint4(hiw[0], hiw[1], hiw[2], hiw[3]);
            *(uint4*)&sAl[r * KP + c * 8] = make_uint4(low[0], low[1], low[2], low[3]);
        }
        __syncthreads();

        float d[2][8][4];
#pragma unroll
        for (int mt = 0; mt < 2; mt++)
#pragma unroll
            for (int nt = 0; nt < 8; nt++)
#pragma unroll
                for (int j = 0; j < 4; j++) d[mt][nt][j] = 0.f;

#pragma unroll
        for (int term = 0; term < 3; term++) {
            uint32_t Abase = sbase + ((term == 2) ? 1 : 0) * 128 * KP * 2;
            uint32_t Bbase = sbase + 2 * 128 * KP * 2 + ((term == 1) ? 1 : 0) * 128 * KP * 2;
#pragma unroll
            for (int ks = 0; ks < 8; ks++) {
                uint32_t a[2][4];
#pragma unroll
                for (int mt = 0; mt < 2; mt++)
                    ldsm_x4(a[mt], Abase + (uint32_t)(((aRow + mt * 16) * KP) + ks * 16 + aKoff) * 2);
                uint32_t b[8][2];
#pragma unroll
                for (int nt2 = 0; nt2 < 4; nt2++) {
                    uint32_t r4[4];
                    ldsm_x4(r4, Bbase + (uint32_t)(((bRow + nt2 * 16) * KP) + ks * 16 + bKoff) * 2);
                    b[nt2 * 2 + 0][0] = r4[0]; b[nt2 * 2 + 0][1] = r4[1];
                    b[nt2 * 2 + 1][0] = r4[2]; b[nt2 * 2 + 1][1] = r4[3];
                }
#pragma unroll
                for (int mt = 0; mt < 2; mt++)
#pragma unroll
                    for (int nt = 0; nt < 8; nt++)
                        mma16816(d[mt][nt], a[mt], b[nt]);
            }
        }

        // epilogue (registers only)
#pragma unroll
        for (int mt = 0; mt < 2; mt++) {
            int ra = row0 + wm * 32 + mt * 16 + quad;
            int rb = ra + 8;
            float da = 0.f, db = 0.f;
            if (MODE == 0) {
                if (ra < n) da = g_dinv[ra];
                if (rb < n) db = g_dinv[rb];
            }
#pragma unroll
            for (int nt = 0; nt < 8; nt++) {
                int c = wn * 64 + nt * 8 + tq * 2;
                float b0 = bias[c], b1 = bias[c + 1];
                if (MODE == 0) {
                    if (ra < n) {
                        __half2 hv = __floats2half2_rn(fmaxf(d[mt][nt][0] + b0, 0.f) * da,
                                                       fmaxf(d[mt][nt][1] + b1, 0.f) * da);
                        *(uint32_t*)&g_h[(size_t)ra * 128 + c] = *reinterpret_cast<uint32_t*>(&hv);
                    }
                    if (rb < n) {
                        __half2 hv = __floats2half2_rn(fmaxf(d[mt][nt][2] + b0, 0.f) * db,
                                                       fmaxf(d[mt][nt][3] + b1, 0.f) * db);
                        *(uint32_t*)&g_h[(size_t)rb * 128 + c] = *reinterpret_cast<uint32_t*>(&hv);
                    }
                } else {
                    float* dst = (c < 64) ? out0 : out1;
                    int cc = (c < 64) ? c : c - 64;
                    if (ra < n) {
                        float2 v = make_float2(d[mt][nt][0] + b0, d[mt][nt][1] + b1);
                        *(float2*)&dst[(size_t)ra * 64 + cc] = v;
                    }
                    if (rb < n) {
                        float2 v = make_float2(d[mt][nt][2] + b0, d[mt][nt][3] + b1);
                        *(float2*)&dst[(size_t)rb * 64 + cc] = v;
                    }
                }
            }
        }
    }
}

// ================= launch =================
#define SM_TOTAL (4 * 128 * KP * 2)

extern "C" void kernel_launch(void* const* d_in, const int* in_sizes, int n_in,
                              void* d_out, int out_size) {
    const float* x   = (const float*)d_in[0];
    const int*   ei  = (const int*)d_in[1];
    const float* W1  = (const float*)d_in[3];
    const float* b1  = (const float*)d_in[4];
    const float* Wmu = (const float*)d_in[5];
    const float* bmu = (const float*)d_in[6];
    const float* Wls = (const float*)d_in[7];
    const float* bls = (const float*)d_in[8];
    float* out = (float*)d_out;

    int n = in_sizes[0] / C;
    int e = in_sizes[1] / 2;
    const int* erow = ei;
    const int* ecol = ei + e;

    float* mu = out;
    float* ls = out + (size_t)n * 64;

    int nb_n = (n + 255) / 256;
    int nb_e4 = ((e + 3) / 4 + 255) / 256;

    cudaFuncSetAttribute(mma_gemm_kernel<0>, cudaFuncAttributeMaxDynamicSharedMemorySize, SM_TOTAL);
    cudaFuncSetAttribute(mma_gemm_kernel<1>, cudaFuncAttributeMaxDynamicSharedMemorySize, SM_TOTAL);

    init_pack_kernel<<<nb_n + 256, 256>>>(n, nb_n, W1, Wmu, bmu, Wls, bls);
    count_kernel<<<nb_e4, 256>>>(ecol, e);
    scanA_kernel<<<nb_n, 256>>>(n);
    scanB_kernel<<<1, NBMAX>>>(nb_n, n);
    scanC_kernel<<<nb_n, 256>>>(x, n);
    scatter_kernel<<<nb_e4, 256>>>(erow, ecol, e);

    int agg_blocks = (n + 7) / 8;

    agg_kernel<0><<<agg_blocks, 256>>>(n);
    mma_gemm_kernel<0><<<GEMM_GRID, 256, SM_TOTAL>>>(b1, nullptr, nullptr, n);
    agg_kernel<1><<<agg_blocks, 256>>>(n);
    mma_gemm_kernel<1><<<GEMM_GRID, 256, SM_TOTAL>>>(nullptr, mu, ls, n);
}

// round 15
// speedup vs baseline: 1.1315x; 1.1315x over previous
#include <cuda_runtime.h>
#include <cuda_bf16.h>
#include <cuda_fp16.h>
#include <cstdint>

#define MAXN 100000
#define MAXE 1600000
#define C 128
#define KP 136   // padded K row length (bf16): 272B rows -> conflict-free ldmatrix
#define GEMM_GRID 148
#define SLOTS 64          // padded adjacency slots per node (Poisson(16) max deg ~45)
#define SPILLMAX 65536

// ================= static scratch =================
__device__ int   g_cnt[MAXN];
__device__ float g_dinv[MAXN];
__device__ int   g_slot[(size_t)MAXN * SLOTS];   // padded adjacency (src per in-edge)
__device__ int   g_spillcnt;
__device__ int2  g_spill[SPILLMAX];              // (target, src) for deg > SLOTS
__device__ __half g_xh[(size_t)MAXN * C];   // dinv-scaled x in fp16
__device__ __half g_h [(size_t)MAXN * C];   // dinv*relu(layer1) in fp16
__device__ __half g_ax[(size_t)MAXN * C];   // agg(x) fp16
__device__ __half g_ah[(size_t)MAXN * C];   // agg(h) fp16
__device__ __nv_bfloat16 g_w1hi[C * C], g_w1lo[C * C];  // W1^T  [n][k] bf16 hi/lo
__device__ __nv_bfloat16 g_w2hi[C * C], g_w2lo[C * C];  // [Wmu|Wls]^T
__device__ float g_b2[C];

// ================= helpers =================
__device__ __forceinline__ uint32_t smem_u32(const void* p) {
    uint32_t a;
    asm("{ .reg .u64 t; cvta.to.shared.u64 t, %1; cvt.u32.u64 %0, t; }" : "=r"(a) : "l"(p));
    return a;
}
__device__ __forceinline__ void ldsm_x4(uint32_t* r, uint32_t addr) {
    asm volatile("ldmatrix.sync.aligned.m8n8.x4.shared.b16 {%0,%1,%2,%3}, [%4];"
        : "=r"(r[0]), "=r"(r[1]), "=r"(r[2]), "=r"(r[3]) : "r"(addr));
}
__device__ __forceinline__ void mma16816(float* d, const uint32_t* a, const uint32_t* b) {
    asm volatile("mma.sync.aligned.m16n8k16.row.col.f32.bf16.bf16.f32 "
        "{%0,%1,%2,%3}, {%4,%5,%6,%7}, {%8,%9}, {%0,%1,%2,%3};"
        : "+f"(d[0]), "+f"(d[1]), "+f"(d[2]), "+f"(d[3])
        : "r"(a[0]), "r"(a[1]), "r"(a[2]), "r"(a[3]), "r"(b[0]), "r"(b[1]));
}
__device__ __forceinline__ uint32_t pack_bf2(float a, float b) {
    __nv_bfloat162 t = __halves2bfloat162(__float2bfloat16_rn(a), __float2bfloat16_rn(b));
    return *reinterpret_cast<uint32_t*>(&t);
}
__device__ __forceinline__ float4 h4f(uint2 u) {
    float2 fa = __half22float2(*reinterpret_cast<__half2*>(&u.x));
    float2 fb = __half22float2(*reinterpret_cast<__half2*>(&u.y));
    return make_float4(fa.x, fa.y, fb.x, fb.y);
}

// ================= build =================
// zero cnt/spillcnt + pack W images (independent work, one launch)
__global__ void init_pack_kernel(int n, int nb_n,
                                 const float* __restrict__ W1,
                                 const float* __restrict__ Wmu, const float* __restrict__ bmu,
                                 const float* __restrict__ Wls, const float* __restrict__ bls) {
    if ((int)blockIdx.x < nb_n) {
        int i = blockIdx.x * blockDim.x + threadIdx.x;
        if (i < n) g_cnt[i] = 0;
        if (blockIdx.x == 0 && threadIdx.x == 0) g_spillcnt = 0;
    } else {
        int pb = blockIdx.x - nb_n;          // 0..255
        int k = pb & 127;
        int layer = pb >> 7;
        int nn = threadIdx.x;
        if (nn < 128) {
            float w;
            if (layer == 0) w = W1[k * 128 + nn];
            else            w = (nn < 64) ? Wmu[k * 64 + nn] : Wls[k * 64 + (nn - 64)];
            __nv_bfloat16 bh = __float2bfloat16_rn(w);
            __nv_bfloat16 bl = __float2bfloat16_rn(w - __bfloat162float(bh));
            if (layer == 0) { g_w1hi[nn * 128 + k] = bh; g_w1lo[nn * 128 + k] = bl; }
            else {
                g_w2hi[nn * 128 + k] = bh; g_w2lo[nn * 128 + k] = bl;
                if (k == 0) g_b2[nn] = (nn < 64) ? bmu[nn] : bls[nn - 64];
            }
        }
    }
}

// single edge pass: count + direct slot placement (spill for deg > SLOTS)
__global__ void count_scatter_kernel(const int* __restrict__ row, const int* __restrict__ col, int e) {
    int i = blockIdx.x * blockDim.x + threadIdx.x;
    if (i < e) {
        int c = col[i];
        int r = atomicAdd(&g_cnt[c], 1);
        if (r < SLOTS) {
            g_slot[(size_t)c * SLOTS + r] = row[i];
        } else {
            int s = atomicAdd(&g_spillcnt, 1);
            if (s < SPILLMAX) g_spill[s] = make_int2(c, row[i]);
        }
    }
}

// dinv + fused x->fp16 pre-scale (streaming, 256 nodes/block)
__global__ void dinv_scale_kernel(const float* __restrict__ x, int n) {
    __shared__ float sd[256];
    int i = blockIdx.x * 256 + threadIdx.x;
    float d = 0.f;
    if (i < n) {
        d = rsqrtf((float)(g_cnt[i] + 1));
        g_dinv[i] = d;
    }
    sd[threadIdx.x] = d;
    __syncthreads();

    size_t base = (size_t)blockIdx.x * 256;
    int lim = n - (int)base; if (lim > 256) lim = 256;
    if (lim <= 0) return;
    for (int j = threadIdx.x; j < lim * 32; j += 256) {
        int local = j >> 5;
        float dv = sd[local];
        float4 v = ((const float4*)x)[(base + local) * 32 + (j & 31)];
        __half2 a = __floats2half2_rn(v.x * dv, v.y * dv);
        __half2 b = __floats2half2_rn(v.z * dv, v.w * dv);
        ((uint2*)g_xh)[(base + local) * 32 + (j & 31)] =
            make_uint2(*reinterpret_cast<uint32_t*>(&a), *reinterpret_cast<uint32_t*>(&b));
    }
}

// ================= aggregation: warp/node, MLP=8 fp16 gather (R13 form) ============
// PHASE 0: src = g_xh -> g_ax       PHASE 1: src = g_h -> g_ah
template <int PHASE>
__global__ void agg_kernel(int n) {
    int w = (blockIdx.x * blockDim.x + threadIdx.x) >> 5;
    int lane = threadIdx.x & 31;
    if (w >= n) return;
    const uint2* __restrict__ s2 = (PHASE == 0) ? (const uint2*)g_xh : (const uint2*)g_h;
    const int* __restrict__ slot = g_slot + (size_t)w * SLOTS;

    float dw = g_dinv[w];
    float4 acc = h4f(s2[(size_t)w * 32 + lane]);   // self term (pre-scaled by dinv)

    int cnt = g_cnt[w];
    int end = (cnt < SLOTS) ? cnt : SLOTS;
    int p = 0;
    for (; p + 8 <= end; p += 8) {
        int s[8];
#pragma unroll
        for (int j = 0; j < 8; j++) s[j] = slot[p + j];
        uint2 v[8];
#pragma unroll
        for (int j = 0; j < 8; j++) v[j] = s2[(size_t)s[j] * 32 + lane];
#pragma unroll
        for (int j = 0; j < 8; j++) {
            float4 f = h4f(v[j]);
            acc.x += f.x; acc.y += f.y; acc.z += f.z; acc.w += f.w;
        }
    }
    for (; p + 4 <= end; p += 4) {
        int s[4];
#pragma unroll
        for (int j = 0; j < 4; j++) s[j] = slot[p + j];
        uint2 v[4];
#pragma unroll
        for (int j = 0; j < 4; j++) v[j] = s2[(size_t)s[j] * 32 + lane];
#pragma unroll
        for (int j = 0; j < 4; j++) {
            float4 f = h4f(v[j]);
            acc.x += f.x; acc.y += f.y; acc.z += f.z; acc.w += f.w;
        }
    }
    for (; p < end; p++) {
        float4 f = h4f(s2[(size_t)slot[p] * 32 + lane]);
        acc.x += f.x; acc.y += f.y; acc.z += f.z; acc.w += f.w;
    }
    acc.x *= dw; acc.y *= dw; acc.z *= dw; acc.w *= dw;

    __half2 a = __floats2half2_rn(acc.x, acc.y);
    __half2 b = __floats2half2_rn(acc.z, acc.w);
    uint2* dst = (uint2*)((PHASE == 0) ? g_ax : g_ah);
    dst[(size_t)w * 32 + lane] = make_uint2(*reinterpret_cast<uint32_t*>(&a),
                                            *reinterpret_cast<uint32_t*>(&b));
}

// spill fixup: add dinv[c] * src_row to agg output for edges beyond SLOTS.
// Runs after agg<PHASE>; one warp per spill edge. g_spillcnt is 0 in practice.
template <int PHASE>
__global__ void spill_fix_kernel() {
    int nspill = g_spillcnt;
    if (nspill > SPILLMAX) nspill = SPILLMAX;
    int widx = (blockIdx.x * blockDim.x + threadIdx.x) >> 5;
    int lane = threadIdx.x & 31;
    if (widx >= nspill) return;
    int2 sp = g_spill[widx];
    const uint2* __restrict__ s2 = (PHASE == 0) ? (const uint2*)g_xh : (const uint2*)g_h;
    uint2* dst = (uint2*)((PHASE == 0) ? g_ax : g_ah);
    float dw = g_dinv[sp.x];
    float4 add = h4f(s2[(size_t)sp.y * 32 + lane]);
    float4 cur = h4f(dst[(size_t)sp.x * 32 + lane]);
    cur.x += dw * add.x; cur.y += dw * add.y;
    cur.z += dw * add.z; cur.w += dw * add.w;
    __half2 a = __floats2half2_rn(cur.x, cur.y);
    __half2 b = __floats2half2_rn(cur.z, cur.w);
    dst[(size_t)sp.x * 32 + lane] = make_uint2(*reinterpret_cast<uint32_t*>(&a),
                                               *reinterpret_cast<uint32_t*>(&b));
}

// ================= persistent HMMA GEMM: B staged once, loop row tiles =============
// A read as fp16, split exactly into bf16 hi/lo during staging.
// MODE 0: A = g_ax, B = W1; epilogue g_h(fp16) = dinv*relu(D+b1)
// MODE 1: A = g_ah, B = W2; split -> mu / logstd (+g_b2)
template <int MODE>
__global__ void __launch_bounds__(256) mma_gemm_kernel(const float* __restrict__ bias1,
                                                       float* __restrict__ out0,
                                                       float* __restrict__ out1, int n) {
    extern __shared__ __align__(16) char smem[];
    __nv_bfloat16* sAh = (__nv_bfloat16*)smem;      // 128 x KP
    __nv_bfloat16* sAl = sAh + 128 * KP;
    __nv_bfloat16* sBh = sAl + 128 * KP;
    __nv_bfloat16* sBl = sBh + 128 * KP;
    int tid = threadIdx.x;
    int lane = tid & 31, wid = tid >> 5;

    // stage B once (persistent)
    {
        const uint4* gBh = (const uint4*)((MODE == 0) ? g_w1hi : g_w2hi);
        const uint4* gBl = (const uint4*)((MODE == 0) ? g_w1lo : g_w2lo);
        for (int i = tid; i < 128 * 16; i += 256) {
            int r = i >> 4, c = i & 15;
            *(uint4*)&sBh[r * KP + c * 8] = gBh[i];
            *(uint4*)&sBl[r * KP + c * 8] = gBl[i];
        }
    }

    const uint4* gA = (const uint4*)((MODE == 0) ? g_ax : g_ah);
    const float* bias = (MODE == 0) ? bias1 : g_b2;

    int wm = wid & 3;
    int wn = wid >> 2;
    uint32_t sbase = smem_u32(smem);
    int aRow  = wm * 32 + (lane & 15);
    int aKoff = (lane >> 4) << 3;
    int bRow  = wn * 64 + ((lane >> 4) << 3) + (lane & 7);
    int bKoff = ((lane >> 3) & 1) << 3;
    int quad = lane >> 2, tq = lane & 3;

    int ntiles = (n + 127) >> 7;
    for (int tile = blockIdx.x; tile < ntiles; tile += gridDim.x) {
        int row0 = tile << 7;
        __syncthreads();   // previous iteration's ldsm of sA complete
        for (int i = tid; i < 128 * 16; i += 256) {
            int r = i >> 4, c = i & 15;
            uint4 v = (row0 + r < n) ? gA[(size_t)(row0 + r) * 16 + c] : make_uint4(0, 0, 0, 0);
            // split 8 fp16 -> bf16 hi/lo (exact: fp16 mantissa fits in hi+lo)
            const __half2* hp = (const __half2*)&v;
            uint32_t hiw[4], low[4];
#pragma unroll
            for (int q = 0; q < 4; q++) {
                float2 f = __half22float2(hp[q]);
                __nv_bfloat16 bx = __float2bfloat16_rn(f.x);
                __nv_bfloat16 by = __float2bfloat16_rn(f.y);
                __nv_bfloat162 hv = __halves2bfloat162(bx, by);
                hiw[q] = *reinterpret_cast<uint32_t*>(&hv);
                low[q] = pack_bf2(f.x - __bfloat162float(bx), f.y - __bfloat162float(by));
            }
            *(uint4*)&sAh[r * KP + c * 8] = make_uint4(hiw[0], hiw[1], hiw[2], hiw[3]);
            *(uint4*)&sAl[r * KP + c * 8] = make_uint4(low[0], low[1], low[2], low[3]);
        }
        __syncthreads();

        float d[2][8][4];
#pragma unroll
        for (int mt = 0; mt < 2; mt++)
#pragma unroll
            for (int nt = 0; nt < 8; nt++)
#pragma unroll
                for (int j = 0; j < 4; j++) d[mt][nt][j] = 0.f;

#pragma unroll
        for (int term = 0; term < 3; term++) {
            uint32_t Abase = sbase + ((term == 2) ? 1 : 0) * 128 * KP * 2;
            uint32_t Bbase = sbase + 2 * 128 * KP * 2 + ((term == 1) ? 1 : 0) * 128 * KP * 2;
#pragma unroll
            for (int ks = 0; ks < 8; ks++) {
                uint32_t a[2][4];
#pragma unroll
                for (int mt = 0; mt < 2; mt++)
                    ldsm_x4(a[mt], Abase + (uint32_t)(((aRow + mt * 16) * KP) + ks * 16 + aKoff) * 2);
                uint32_t b[8][2];
#pragma unroll
                for (int nt2 = 0; nt2 < 4; nt2++) {
                    uint32_t r4[4];
                    ldsm_x4(r4, Bbase + (uint32_t)(((bRow + nt2 * 16) * KP) + ks * 16 + bKoff) * 2);
                    b[nt2 * 2 + 0][0] = r4[0]; b[nt2 * 2 + 0][1] = r4[1];
                    b[nt2 * 2 + 1][0] = r4[2]; b[nt2 * 2 + 1][1] = r4[3];
                }
#pragma unroll
                for (int mt = 0; mt < 2; mt++)
#pragma unroll
                    for (int nt = 0; nt < 8; nt++)
                        mma16816(d[mt][nt], a[mt], b[nt]);
            }
        }

        // epilogue (registers only)
#pragma unroll
        for (int mt = 0; mt < 2; mt++) {
            int ra = row0 + wm * 32 + mt * 16 + quad;
            int rb = ra + 8;
            float da = 0.f, db = 0.f;
            if (MODE == 0) {
                if (ra < n) da = g_dinv[ra];
                if (rb < n) db = g_dinv[rb];
            }
#pragma unroll
            for (int nt = 0; nt < 8; nt++) {
                int c = wn * 64 + nt * 8 + tq * 2;
                float b0 = bias[c], b1 = bias[c + 1];
                if (MODE == 0) {
                    if (ra < n) {
                        __half2 hv = __floats2half2_rn(fmaxf(d[mt][nt][0] + b0, 0.f) * da,
                                                       fmaxf(d[mt][nt][1] + b1, 0.f) * da);
                        *(uint32_t*)&g_h[(size_t)ra * 128 + c] = *reinterpret_cast<uint32_t*>(&hv);
                    }
                    if (rb < n) {
                        __half2 hv = __floats2half2_rn(fmaxf(d[mt][nt][2] + b0, 0.f) * db,
                                                       fmaxf(d[mt][nt][3] + b1, 0.f) * db);
                        *(uint32_t*)&g_h[(size_t)rb * 128 + c] = *reinterpret_cast<uint32_t*>(&hv);
                    }
                } else {
                    float* dst = (c < 64) ? out0 : out1;
                    int cc = (c < 64) ? c : c - 64;
                    if (ra < n) {
                        float2 v = make_float2(d[mt][nt][0] + b0, d[mt][nt][1] + b1);
                        *(float2*)&dst[(size_t)ra * 64 + cc] = v;
                    }
                    if (rb < n) {
                        float2 v = make_float2(d[mt][nt][2] + b0, d[mt][nt][3] + b1);
                        *(float2*)&dst[(size_t)rb * 64 + cc] = v;
                    }
                }
            }
        }
    }
}

// ================= launch =================
#define SM_TOTAL (4 * 128 * KP * 2)

extern "C" void kernel_launch(void* const* d_in, const int* in_sizes, int n_in,
                              void* d_out, int out_size) {
    const float* x   = (const float*)d_in[0];
    const int*   ei  = (const int*)d_in[1];
    const float* W1  = (const float*)d_in[3];
    const float* b1  = (const float*)d_in[4];
    const float* Wmu = (const float*)d_in[5];
    const float* bmu = (const float*)d_in[6];
    const float* Wls = (const float*)d_in[7];
    const float* bls = (const float*)d_in[8];
    float* out = (float*)d_out;

    int n = in_sizes[0] / C;
    int e = in_sizes[1] / 2;
    const int* erow = ei;
    const int* ecol = ei + e;

    float* mu = out;
    float* ls = out + (size_t)n * 64;

    int nb_n = (n + 255) / 256;
    int nb_e = (e + 255) / 256;

    cudaFuncSetAttribute(mma_gemm_kernel<0>, cudaFuncAttributeMaxDynamicSharedMemorySize, SM_TOTAL);
    cudaFuncSetAttribute(mma_gemm_kernel<1>, cudaFuncAttributeMaxDynamicSharedMemorySize, SM_TOTAL);

    init_pack_kernel<<<nb_n + 256, 256>>>(n, nb_n, W1, Wmu, bmu, Wls, bls);
    count_scatter_kernel<<<nb_e, 256>>>(erow, ecol, e);
    dinv_scale_kernel<<<nb_n, 256>>>(x, n);

    int agg_blocks = (n + 7) / 8;
    int spill_blocks = (SPILLMAX * 32 + 255) / 256;   // upper bound; exits fast when empty

    agg_kernel<0><<<agg_blocks, 256>>>(n);
    spill_fix_kernel<0><<<spill_blocks, 256>>>();
    mma_gemm_kernel<0><<<GEMM_GRID, 256, SM_TOTAL>>>(b1, nullptr, nullptr, n);
    agg_kernel<1><<<agg_blocks, 256>>>(n);
    spill_fix_kernel<1><<<spill_blocks, 256>>>();
    mma_gemm_kernel<1><<<GEMM_GRID, 256, SM_TOTAL>>>(nullptr, mu, ls, n);
}

// round 16
// speedup vs baseline: 1.1962x; 1.0572x over previous
#include <cuda_runtime.h>
#include <cuda_bf16.h>
#include <cuda_fp16.h>
#include <cstdint>

#define MAXN 100000
#define MAXE 1600000
#define C 128
#define KP 136   // padded K row length (bf16): 272B rows -> conflict-free ldmatrix
#define GEMM_GRID 148
#define SLOTS 64          // padded adjacency slots per node (Poisson(16) max deg ~45)
#define SPILLMAX 65536

// ================= static scratch =================
__device__ int   g_cnt[MAXN];
__device__ float g_dinv[MAXN];
__device__ int   g_slot[(size_t)MAXN * SLOTS];   // padded adjacency (src per in-edge)
__device__ int   g_spillcnt;
__device__ int2  g_spill[SPILLMAX];              // (target, src) for deg > SLOTS
__device__ __half g_xh[(size_t)MAXN * C];   // dinv-scaled x in fp16
__device__ __half g_h [(size_t)MAXN * C];   // dinv*relu(layer1) in fp16
__device__ __half g_ax[(size_t)MAXN * C];   // agg(x) fp16
__device__ __half g_ah[(size_t)MAXN * C];   // agg(h) fp16
__device__ __nv_bfloat16 g_w1hi[C * C], g_w1lo[C * C];  // W1^T  [n][k] bf16 hi/lo
__device__ __nv_bfloat16 g_w2hi[C * C], g_w2lo[C * C];  // [Wmu|Wls]^T
__device__ float g_b2[C];

// ================= helpers =================
__device__ __forceinline__ uint32_t smem_u32(const void* p) {
    uint32_t a;
    asm("{ .reg .u64 t; cvta.to.shared.u64 t, %1; cvt.u32.u64 %0, t; }" : "=r"(a) : "l"(p));
    return a;
}
__device__ __forceinline__ void ldsm_x4(uint32_t* r, uint32_t addr) {
    asm volatile("ldmatrix.sync.aligned.m8n8.x4.shared.b16 {%0,%1,%2,%3}, [%4];"
        : "=r"(r[0]), "=r"(r[1]), "=r"(r[2]), "=r"(r[3]) : "r"(addr));
}
__device__ __forceinline__ void mma16816(float* d, const uint32_t* a, const uint32_t* b) {
    asm volatile("mma.sync.aligned.m16n8k16.row.col.f32.bf16.bf16.f32 "
        "{%0,%1,%2,%3}, {%4,%5,%6,%7}, {%8,%9}, {%0,%1,%2,%3};"
        : "+f"(d[0]), "+f"(d[1]), "+f"(d[2]), "+f"(d[3])
        : "r"(a[0]), "r"(a[1]), "r"(a[2]), "r"(a[3]), "r"(b[0]), "r"(b[1]));
}
__device__ __forceinline__ uint32_t pack_bf2(float a, float b) {
    __nv_bfloat162 t = __halves2bfloat162(__float2bfloat16_rn(a), __float2bfloat16_rn(b));
    return *reinterpret_cast<uint32_t*>(&t);
}
__device__ __forceinline__ float4 h4f(uint2 u) {
    float2 fa = __half22float2(*reinterpret_cast<__half2*>(&u.x));
    float2 fb = __half22float2(*reinterpret_cast<__half2*>(&u.y));
    return make_float4(fa.x, fa.y, fb.x, fb.y);
}

// ================= build =================
// zero cnt/spillcnt + pack W images (independent work, one launch)
__global__ void init_pack_kernel(int n, int nb_n,
                                 const float* __restrict__ W1,
                                 const float* __restrict__ Wmu, const float* __restrict__ bmu,
                                 const float* __restrict__ Wls, const float* __restrict__ bls) {
    if ((int)blockIdx.x < nb_n) {
        int i = blockIdx.x * blockDim.x + threadIdx.x;
        if (i < n) g_cnt[i] = 0;
        if (blockIdx.x == 0 && threadIdx.x == 0) g_spillcnt = 0;
    } else {
        int pb = blockIdx.x - nb_n;          // 0..255
        int k = pb & 127;
        int layer = pb >> 7;
        int nn = threadIdx.x;
        if (nn < 128) {
            float w;
            if (layer == 0) w = W1[k * 128 + nn];
            else            w = (nn < 64) ? Wmu[k * 64 + nn] : Wls[k * 64 + (nn - 64)];
            __nv_bfloat16 bh = __float2bfloat16_rn(w);
            __nv_bfloat16 bl = __float2bfloat16_rn(w - __bfloat162float(bh));
            if (layer == 0) { g_w1hi[nn * 128 + k] = bh; g_w1lo[nn * 128 + k] = bl; }
            else {
                g_w2hi[nn * 128 + k] = bh; g_w2lo[nn * 128 + k] = bl;
                if (k == 0) g_b2[nn] = (nn < 64) ? bmu[nn] : bls[nn - 64];
            }
        }
    }
}

// single edge pass: count + direct slot placement (spill for deg > SLOTS)
__global__ void count_scatter_kernel(const int* __restrict__ row, const int* __restrict__ col, int e) {
    int i = blockIdx.x * blockDim.x + threadIdx.x;
    if (i < e) {
        int c = col[i];
        int r = atomicAdd(&g_cnt[c], 1);
        if (r < SLOTS) {
            g_slot[(size_t)c * SLOTS + r] = row[i];
        } else {
            int s = atomicAdd(&g_spillcnt, 1);
            if (s < SPILLMAX) g_spill[s] = make_int2(c, row[i]);
        }
    }
}

// dinv + fused x->fp16 pre-scale (streaming, 256 nodes/block)
__global__ void dinv_scale_kernel(const float* __restrict__ x, int n) {
    __shared__ float sd[256];
    int i = blockIdx.x * 256 + threadIdx.x;
    float d = 0.f;
    if (i < n) {
        d = rsqrtf((float)(g_cnt[i] + 1));
        g_dinv[i] = d;
    }
    sd[threadIdx.x] = d;
    __syncthreads();

    size_t base = (size_t)blockIdx.x * 256;
    int lim = n - (int)base; if (lim > 256) lim = 256;
    if (lim <= 0) return;
    for (int j = threadIdx.x; j < lim * 32; j += 256) {
        int local = j >> 5;
        float dv = sd[local];
        float4 v = ((const float4*)x)[(base + local) * 32 + (j & 31)];
        __half2 a = __floats2half2_rn(v.x * dv, v.y * dv);
        __half2 b = __floats2half2_rn(v.z * dv, v.w * dv);
        ((uint2*)g_xh)[(base + local) * 32 + (j & 31)] =
            make_uint2(*reinterpret_cast<uint32_t*>(&a), *reinterpret_cast<uint32_t*>(&b));
    }
}

// ================= aggregation: warp/node, pairwise HADD2 + fp32 accumulate ========
// Per edge pair: add the two fp16 rows with HADD2 (1 instr/half2), then one
// convert+accumulate into fp32. Cuts the convert/add chain from 8 to 4 instrs/edge.
// PHASE 0: src = g_xh -> g_ax       PHASE 1: src = g_h -> g_ah
template <int PHASE>
__global__ void agg_kernel(int n) {
    int w = (blockIdx.x * blockDim.x + threadIdx.x) >> 5;
    int lane = threadIdx.x & 31;
    if (w >= n) return;
    const uint2* __restrict__ s2 = (PHASE == 0) ? (const uint2*)g_xh : (const uint2*)g_h;
    const int* __restrict__ slot = g_slot + (size_t)w * SLOTS;

    float dw = g_dinv[w];
    float4 acc = h4f(s2[(size_t)w * 32 + lane]);   // self term (pre-scaled by dinv)

    int cnt = g_cnt[w];
    int end = (cnt < SLOTS) ? cnt : SLOTS;
    int p = 0;
    // batches of 8 edges, processed as 4 HADD2 pairs
    for (; p + 8 <= end; p += 8) {
        int s[8];
#pragma unroll
        for (int j = 0; j < 8; j++) s[j] = slot[p + j];
        uint2 v[8];
#pragma unroll
        for (int j = 0; j < 8; j++) v[j] = s2[(size_t)s[j] * 32 + lane];
#pragma unroll
        for (int j = 0; j < 4; j++) {
            __half2 pa = __hadd2(*reinterpret_cast<__half2*>(&v[2 * j].x),
                                 *reinterpret_cast<__half2*>(&v[2 * j + 1].x));
            __half2 pb = __hadd2(*reinterpret_cast<__half2*>(&v[2 * j].y),
                                 *reinterpret_cast<__half2*>(&v[2 * j + 1].y));
            float2 f0 = __half22float2(pa);
            float2 f1 = __half22float2(pb);
            acc.x += f0.x; acc.y += f0.y; acc.z += f1.x; acc.w += f1.y;
        }
    }
    // pairs
    for (; p + 2 <= end; p += 2) {
        int s0 = slot[p], s1 = slot[p + 1];
        uint2 v0 = s2[(size_t)s0 * 32 + lane];
        uint2 v1 = s2[(size_t)s1 * 32 + lane];
        __half2 pa = __hadd2(*reinterpret_cast<__half2*>(&v0.x),
                             *reinterpret_cast<__half2*>(&v1.x));
        __half2 pb = __hadd2(*reinterpret_cast<__half2*>(&v0.y),
                             *reinterpret_cast<__half2*>(&v1.y));
        float2 f0 = __half22float2(pa);
        float2 f1 = __half22float2(pb);
        acc.x += f0.x; acc.y += f0.y; acc.z += f1.x; acc.w += f1.y;
    }
    // final odd edge: exact fp32 path
    if (p < end) {
        float4 f = h4f(s2[(size_t)slot[p] * 32 + lane]);
        acc.x += f.x; acc.y += f.y; acc.z += f.z; acc.w += f.w;
    }
    acc.x *= dw; acc.y *= dw; acc.z *= dw; acc.w *= dw;

    __half2 a = __floats2half2_rn(acc.x, acc.y);
    __half2 b = __floats2half2_rn(acc.z, acc.w);
    uint2* dst = (uint2*)((PHASE == 0) ? g_ax : g_ah);
    dst[(size_t)w * 32 + lane] = make_uint2(*reinterpret_cast<uint32_t*>(&a),
                                            *reinterpret_cast<uint32_t*>(&b));
}

// spill fixup: add dinv[c] * src_row to agg output for edges beyond SLOTS.
// Warp-strided loop; near-zero cost when spill list is empty (the common case).
template <int PHASE>
__global__ void spill_fix_kernel() {
    int nspill = g_spillcnt;
    if (nspill > SPILLMAX) nspill = SPILLMAX;
    int lane = threadIdx.x & 31;
    int nwarps = (gridDim.x * blockDim.x) >> 5;
    for (int widx = (blockIdx.x * blockDim.x + threadIdx.x) >> 5; widx < nspill; widx += nwarps) {
        int2 sp = g_spill[widx];
        const uint2* __restrict__ s2 = (PHASE == 0) ? (const uint2*)g_xh : (const uint2*)g_h;
        uint2* dst = (uint2*)((PHASE == 0) ? g_ax : g_ah);
        float dw = g_dinv[sp.x];
        float4 add = h4f(s2[(size_t)sp.y * 32 + lane]);
        float4 cur = h4f(dst[(size_t)sp.x * 32 + lane]);
        cur.x += dw * add.x; cur.y += dw * add.y;
        cur.z += dw * add.z; cur.w += dw * add.w;
        __half2 a = __floats2half2_rn(cur.x, cur.y);
        __half2 b = __floats2half2_rn(cur.z, cur.w);
        dst[(size_t)sp.x * 32 + lane] = make_uint2(*reinterpret_cast<uint32_t*>(&a),
                                                   *reinterpret_cast<uint32_t*>(&b));
    }
}

// ================= persistent HMMA GEMM: B staged once, loop row tiles =============
// A read as fp16, split exactly into bf16 hi/lo during staging.
// MODE 0: A = g_ax, B = W1; epilogue g_h(fp16) = dinv*relu(D+b1)
// MODE 1: A = g_ah, B = W2; split -> mu / logstd (+g_b2)
template <int MODE>
__global__ void __launch_bounds__(256) mma_gemm_kernel(const float* __restrict__ bias1,
                                                       float* __restrict__ out0,
                                                       float* __restrict__ out1, int n) {
    extern __shared__ __align__(16) char smem[];
    __nv_bfloat16* sAh = (__nv_bfloat16*)smem;      // 128 x KP
    __nv_bfloat16* sAl = sAh + 128 * KP;
    __nv_bfloat16* sBh = sAl + 128 * KP;
    __nv_bfloat16* sBl = sBh + 128 * KP;
    int tid = threadIdx.x;
    int lane = tid & 31, wid = tid >> 5;

    // stage B once (persistent)
    {
        const uint4* gBh = (const uint4*)((MODE == 0) ? g_w1hi : g_w2hi);
        const uint4* gBl = (const uint4*)((MODE == 0) ? g_w1lo : g_w2lo);
        for (int i = tid; i < 128 * 16; i += 256) {
            int r = i >> 4, c = i & 15;
            *(uint4*)&sBh[r * KP + c * 8] = gBh[i];
            *(uint4*)&sBl[r * KP + c * 8] = gBl[i];
        }
    }

    const uint4* gA = (const uint4*)((MODE == 0) ? g_ax : g_ah);
    const float* bias = (MODE == 0) ? bias1 : g_b2;

    int wm = wid & 3;
    int wn = wid >> 2;
    uint32_t sbase = smem_u32(smem);
    int aRow  = wm * 32 + (lane & 15);
    int aKoff = (lane >> 4) << 3;
    int bRow  = wn * 64 + ((lane >> 4) << 3) + (lane & 7);
    int bKoff = ((lane >> 3) & 1) << 3;
    int quad = lane >> 2, tq = lane & 3;

    int ntiles = (n + 127) >> 7;
    for (int tile = blockIdx.x; tile < ntiles; tile += gridDim.x) {
        int row0 = tile << 7;
        __syncthreads();   // previous iteration's ldsm of sA complete
        for (int i = tid; i < 128 * 16; i += 256) {
            int r = i >> 4, c = i & 15;
            uint4 v = (row0 + r < n) ? gA[(size_t)(row0 + r) * 16 + c] : make_uint4(0, 0, 0, 0);
            // split 8 fp16 -> bf16 hi/lo (exact: fp16 mantissa fits in hi+lo)
            const __half2* hp = (const __half2*)&v;
            uint32_t hiw[4], low[4];
#pragma unroll
            for (int q = 0; q < 4; q++) {
                float2 f = __half22float2(hp[q]);
                __nv_bfloat16 bx = __float2bfloat16_rn(f.x);
                __nv_bfloat16 by = __float2bfloat16_rn(f.y);
                __nv_bfloat162 hv = __halves2bfloat162(bx, by);
                hiw[q] = *reinterpret_cast<uint32_t*>(&hv);
                low[q] = pack_bf2(f.x - __bfloat162float(bx), f.y - __bfloat162float(by));
            }
            *(uint4*)&sAh[r * KP + c * 8] = make_uint4(hiw[0], hiw[1], hiw[2], hiw[3]);
            *(uint4*)&sAl[r * KP + c * 8] = make_uint4(low[0], low[1], low[2], low[3]);
        }
        __syncthreads();

        float d[2][8][4];
#pragma unroll
        for (int mt = 0; mt < 2; mt++)
#pragma unroll
            for (int nt = 0; nt < 8; nt++)
#pragma unroll
                for (int j = 0; j < 4; j++) d[mt][nt][j] = 0.f;

#pragma unroll
        for (int term = 0; term < 3; term++) {
            uint32_t Abase = sbase + ((term == 2) ? 1 : 0) * 128 * KP * 2;
            uint32_t Bbase = sbase + 2 * 128 * KP * 2 + ((term == 1) ? 1 : 0) * 128 * KP * 2;
#pragma unroll
            for (int ks = 0; ks < 8; ks++) {
                uint32_t a[2][4];
#pragma unroll
                for (int mt = 0; mt < 2; mt++)
                    ldsm_x4(a[mt], Abase + (uint32_t)(((aRow + mt * 16) * KP) + ks * 16 + aKoff) * 2);
                uint32_t b[8][2];
#pragma unroll
                for (int nt2 = 0; nt2 < 4; nt2++) {
                    uint32_t r4[4];
                    ldsm_x4(r4, Bbase + (uint32_t)(((bRow + nt2 * 16) * KP) + ks * 16 + bKoff) * 2);
                    b[nt2 * 2 + 0][0] = r4[0]; b[nt2 * 2 + 0][1] = r4[1];
                    b[nt2 * 2 + 1][0] = r4[2]; b[nt2 * 2 + 1][1] = r4[3];
                }
#pragma unroll
                for (int mt = 0; mt < 2; mt++)
#pragma unroll
                    for (int nt = 0; nt < 8; nt++)
                        mma16816(d[mt][nt], a[mt], b[nt]);
            }
        }

        // epilogue (registers only)
#pragma unroll
        for (int mt = 0; mt < 2; mt++) {
            int ra = row0 + wm * 32 + mt * 16 + quad;
            int rb = ra + 8;
            float da = 0.f, db = 0.f;
            if (MODE == 0) {
                if (ra < n) da = g_dinv[ra];
                if (rb < n) db = g_dinv[rb];
            }
#pragma unroll
            for (int nt = 0; nt < 8; nt++) {
                int c = wn * 64 + nt * 8 + tq * 2;
                float b0 = bias[c], b1 = bias[c + 1];
                if (MODE == 0) {
                    if (ra < n) {
                        __half2 hv = __floats2half2_rn(fmaxf(d[mt][nt][0] + b0, 0.f) * da,
                                                       fmaxf(d[mt][nt][1] + b1, 0.f) * da);
                        *(uint32_t*)&g_h[(size_t)ra * 128 + c] = *reinterpret_cast<uint32_t*>(&hv);
                    }
                    if (rb < n) {
                        __half2 hv = __floats2half2_rn(fmaxf(d[mt][nt][2] + b0, 0.f) * db,
                                                       fmaxf(d[mt][nt][3] + b1, 0.f) * db);
                        *(uint32_t*)&g_h[(size_t)rb * 128 + c] = *reinterpret_cast<uint32_t*>(&hv);
                    }
                } else {
                    float* dst = (c < 64) ? out0 : out1;
                    int cc = (c < 64) ? c : c - 64;
                    if (ra < n) {
                        float2 v = make_float2(d[mt][nt][0] + b0, d[mt][nt][1] + b1);
                        *(float2*)&dst[(size_t)ra * 64 + cc] = v;
                    }
                    if (rb < n) {
                        float2 v = make_float2(d[mt][nt][2] + b0, d[mt][nt][3] + b1);
                        *(float2*)&dst[(size_t)rb * 64 + cc] = v;
                    }
                }
            }
        }
    }
}

// ================= launch =================
#define SM_TOTAL (4 * 128 * KP * 2)

extern "C" void kernel_launch(void* const* d_in, const int* in_sizes, int n_in,
                              void* d_out, int out_size) {
    const float* x   = (const float*)d_in[0];
    const int*   ei  = (const int*)d_in[1];
    const float* W1  = (const float*)d_in[3];
    const float* b1  = (const float*)d_in[4];
    const float* Wmu = (const float*)d_in[5];
    const float* bmu = (const float*)d_in[6];
    const float* Wls = (const float*)d_in[7];
    const float* bls = (const float*)d_in[8];
    float* out = (float*)d_out;

    int n = in_sizes[0] / C;
    int e = in_sizes[1] / 2;
    const int* erow = ei;
    const int* ecol = ei + e;

    float* mu = out;
    float* ls = out + (size_t)n * 64;

    int nb_n = (n + 255) / 256;
    int nb_e = (e + 255) / 256;

    cudaFuncSetAttribute(mma_gemm_kernel<0>, cudaFuncAttributeMaxDynamicSharedMemorySize, SM_TOTAL);
    cudaFuncSetAttribute(mma_gemm_kernel<1>, cudaFuncAttributeMaxDynamicSharedMemorySize, SM_TOTAL);

    init_pack_kernel<<<nb_n + 256, 256>>>(n, nb_n, W1, Wmu, bmu, Wls, bls);
    count_scatter_kernel<<<nb_e, 256>>>(erow, ecol, e);
    dinv_scale_kernel<<<nb_n, 256>>>(x, n);

    int agg_blocks = (n + 7) / 8;

    agg_kernel<0><<<agg_blocks, 256>>>(n);
    spill_fix_kernel<0><<<128, 256>>>();
    mma_gemm_kernel<0><<<GEMM_GRID, 256, SM_TOTAL>>>(b1, nullptr, nullptr, n);
    agg_kernel<1><<<agg_blocks, 256>>>(n);
    spill_fix_kernel<1><<<128, 256>>>();
    mma_gemm_kernel<1><<<GEMM_GRID, 256, SM_TOTAL>>>(nullptr, mu, ls, n);
}

// round 17
// speedup vs baseline: 1.2068x; 1.0089x over previous
#include <cuda_runtime.h>
#include <cuda_bf16.h>
#include <cuda_fp16.h>
#include <cstdint>

#define MAXN 100000
#define MAXE 1600000
#define C 128
#define KP 136   // padded K row length (bf16): 272B rows -> conflict-free ldmatrix
#define GEMM_GRID 148
#define SLOTS 64          // padded adjacency slots per node (Poisson(16) max deg ~45)
#define SPILLMAX 65536

// ================= static scratch =================
__device__ int   g_cnt[MAXN];
__device__ float g_dinv[MAXN];
__device__ int   g_slot[(size_t)MAXN * SLOTS];   // padded adjacency (src per in-edge)
__device__ int   g_spillcnt;
__device__ int2  g_spill[SPILLMAX];              // (target, src) for deg > SLOTS
__device__ __half g_xh[(size_t)MAXN * C];   // dinv-scaled x in fp16
__device__ __half g_h [(size_t)MAXN * C];   // dinv*relu(layer1) in fp16
__device__ __half g_ax[(size_t)MAXN * C];   // agg(x) fp16
__device__ __half g_ah[(size_t)MAXN * C];   // agg(h) fp16
__device__ __nv_bfloat16 g_w1hi[C * C], g_w1lo[C * C];  // W1^T  [n][k] bf16 hi/lo
__device__ __nv_bfloat16 g_w2hi[C * C], g_w2lo[C * C];  // [Wmu|Wls]^T
__device__ float g_b2[C];

// ================= helpers =================
__device__ __forceinline__ uint32_t smem_u32(const void* p) {
    uint32_t a;
    asm("{ .reg .u64 t; cvta.to.shared.u64 t, %1; cvt.u32.u64 %0, t; }" : "=r"(a) : "l"(p));
    return a;
}
__device__ __forceinline__ void ldsm_x4(uint32_t* r, uint32_t addr) {
    asm volatile("ldmatrix.sync.aligned.m8n8.x4.shared.b16 {%0,%1,%2,%3}, [%4];"
        : "=r"(r[0]), "=r"(r[1]), "=r"(r[2]), "=r"(r[3]) : "r"(addr));
}
__device__ __forceinline__ void mma16816(float* d, const uint32_t* a, const uint32_t* b) {
    asm volatile("mma.sync.aligned.m16n8k16.row.col.f32.bf16.bf16.f32 "
        "{%0,%1,%2,%3}, {%4,%5,%6,%7}, {%8,%9}, {%0,%1,%2,%3};"
        : "+f"(d[0]), "+f"(d[1]), "+f"(d[2]), "+f"(d[3])
        : "r"(a[0]), "r"(a[1]), "r"(a[2]), "r"(a[3]), "r"(b[0]), "r"(b[1]));
}
__device__ __forceinline__ uint32_t pack_bf2(float a, float b) {
    __nv_bfloat162 t = __halves2bfloat162(__float2bfloat16_rn(a), __float2bfloat16_rn(b));
    return *reinterpret_cast<uint32_t*>(&t);
}
__device__ __forceinline__ float4 h4f(uint2 u) {
    float2 fa = __half22float2(*reinterpret_cast<__half2*>(&u.x));
    float2 fb = __half22float2(*reinterpret_cast<__half2*>(&u.y));
    return make_float4(fa.x, fa.y, fb.x, fb.y);
}

// ================= build =================
__global__ void init_pack_kernel(int n, int nb_n,
                                 const float* __restrict__ W1,
                                 const float* __restrict__ Wmu, const float* __restrict__ bmu,
                                 const float* __restrict__ Wls, const float* __restrict__ bls) {
    if ((int)blockIdx.x < nb_n) {
        int i = blockIdx.x * blockDim.x + threadIdx.x;
        if (i < n) g_cnt[i] = 0;
        if (blockIdx.x == 0 && threadIdx.x == 0) g_spillcnt = 0;
    } else {
        int pb = blockIdx.x - nb_n;          // 0..255
        int k = pb & 127;
        int layer = pb >> 7;
        int nn = threadIdx.x;
        if (nn < 128) {
            float w;
            if (layer == 0) w = W1[k * 128 + nn];
            else            w = (nn < 64) ? Wmu[k * 64 + nn] : Wls[k * 64 + (nn - 64)];
            __nv_bfloat16 bh = __float2bfloat16_rn(w);
            __nv_bfloat16 bl = __float2bfloat16_rn(w - __bfloat162float(bh));
            if (layer == 0) { g_w1hi[nn * 128 + k] = bh; g_w1lo[nn * 128 + k] = bl; }
            else {
                g_w2hi[nn * 128 + k] = bh; g_w2lo[nn * 128 + k] = bl;
                if (k == 0) g_b2[nn] = (nn < 64) ? bmu[nn] : bls[nn - 64];
            }
        }
    }
}

// single edge pass: count + direct slot placement (spill for deg > SLOTS)
__global__ void count_scatter_kernel(const int* __restrict__ row, const int* __restrict__ col, int e) {
    int i = blockIdx.x * blockDim.x + threadIdx.x;
    if (i < e) {
        int c = col[i];
        int r = atomicAdd(&g_cnt[c], 1);
        if (r < SLOTS) {
            g_slot[(size_t)c * SLOTS + r] = row[i];
        } else {
            int s = atomicAdd(&g_spillcnt, 1);
            if (s < SPILLMAX) g_spill[s] = make_int2(c, row[i]);
        }
    }
}

// dinv + fused x->fp16 pre-scale (streaming, 256 nodes/block)
__global__ void dinv_scale_kernel(const float* __restrict__ x, int n) {
    __shared__ float sd[256];
    int i = blockIdx.x * 256 + threadIdx.x;
    float d = 0.f;
    if (i < n) {
        d = rsqrtf((float)(g_cnt[i] + 1));
        g_dinv[i] = d;
    }
    sd[threadIdx.x] = d;
    __syncthreads();

    size_t base = (size_t)blockIdx.x * 256;
    int lim = n - (int)base; if (lim > 256) lim = 256;
    if (lim <= 0) return;
    for (int j = threadIdx.x; j < lim * 32; j += 256) {
        int local = j >> 5;
        float dv = sd[local];
        float4 v = ((const float4*)x)[(base + local) * 32 + (j & 31)];
        __half2 a = __floats2half2_rn(v.x * dv, v.y * dv);
        __half2 b = __floats2half2_rn(v.z * dv, v.w * dv);
        ((uint2*)g_xh)[(base + local) * 32 + (j & 31)] =
            make_uint2(*reinterpret_cast<uint32_t*>(&a), *reinterpret_cast<uint32_t*>(&b));
    }
}

// ================= aggregation: warp/node, HADD2 pairs + int4 slots + 32-bit idx ====
// PHASE 0: src = g_xh -> g_ax       PHASE 1: src = g_h -> g_ah
template <int PHASE>
__global__ void agg_kernel(int n) {
    int w = (blockIdx.x * blockDim.x + threadIdx.x) >> 5;
    unsigned lane = threadIdx.x & 31;
    if (w >= n) return;
    const uint2* __restrict__ s2 = (PHASE == 0) ? (const uint2*)g_xh : (const uint2*)g_h;
    const int* __restrict__ slot = g_slot + (size_t)w * SLOTS;

    float dw = g_dinv[w];
    float4 acc = h4f(s2[(unsigned)w * 32u + lane]);   // self term (pre-scaled by dinv)

    int cnt = g_cnt[w];
    int end = (cnt < SLOTS) ? cnt : SLOTS;
    int p = 0;
    // batches of 8 edges: 2 int4 slot loads, 8 feature loads (32-bit idx), 4 HADD2 pairs
    for (; p + 8 <= end; p += 8) {
        int4 sa = *(const int4*)(slot + p);
        int4 sb = *(const int4*)(slot + p + 4);
        uint2 v[8];
        v[0] = s2[(unsigned)sa.x * 32u + lane];
        v[1] = s2[(unsigned)sa.y * 32u + lane];
        v[2] = s2[(unsigned)sa.z * 32u + lane];
        v[3] = s2[(unsigned)sa.w * 32u + lane];
        v[4] = s2[(unsigned)sb.x * 32u + lane];
        v[5] = s2[(unsigned)sb.y * 32u + lane];
        v[6] = s2[(unsigned)sb.z * 32u + lane];
        v[7] = s2[(unsigned)sb.w * 32u + lane];
#pragma unroll
        for (int j = 0; j < 4; j++) {
            __half2 pa = __hadd2(*reinterpret_cast<__half2*>(&v[2 * j].x),
                                 *reinterpret_cast<__half2*>(&v[2 * j + 1].x));
            __half2 pb = __hadd2(*reinterpret_cast<__half2*>(&v[2 * j].y),
                                 *reinterpret_cast<__half2*>(&v[2 * j + 1].y));
            float2 f0 = __half22float2(pa);
            float2 f1 = __half22float2(pb);
            acc.x += f0.x; acc.y += f0.y; acc.z += f1.x; acc.w += f1.y;
        }
    }
    // pairs
    for (; p + 2 <= end; p += 2) {
        unsigned s0 = (unsigned)slot[p], s1 = (unsigned)slot[p + 1];
        uint2 v0 = s2[s0 * 32u + lane];
        uint2 v1 = s2[s1 * 32u + lane];
        __half2 pa = __hadd2(*reinterpret_cast<__half2*>(&v0.x),
                             *reinterpret_cast<__half2*>(&v1.x));
        __half2 pb = __hadd2(*reinterpret_cast<__half2*>(&v0.y),
                             *reinterpret_cast<__half2*>(&v1.y));
        float2 f0 = __half22float2(pa);
        float2 f1 = __half22float2(pb);
        acc.x += f0.x; acc.y += f0.y; acc.z += f1.x; acc.w += f1.y;
    }
    // final odd edge: exact fp32 path
    if (p < end) {
        float4 f = h4f(s2[(unsigned)slot[p] * 32u + lane]);
        acc.x += f.x; acc.y += f.y; acc.z += f.z; acc.w += f.w;
    }
    acc.x *= dw; acc.y *= dw; acc.z *= dw; acc.w *= dw;

    __half2 a = __floats2half2_rn(acc.x, acc.y);
    __half2 b = __floats2half2_rn(acc.z, acc.w);
    uint2* dst = (uint2*)((PHASE == 0) ? g_ax : g_ah);
    dst[(unsigned)w * 32u + lane] = make_uint2(*reinterpret_cast<uint32_t*>(&a),
                                               *reinterpret_cast<uint32_t*>(&b));
}

// spill fixup: add dinv[c] * src_row to agg output for edges beyond SLOTS.
template <int PHASE>
__global__ void spill_fix_kernel() {
    int nspill = g_spillcnt;
    if (nspill > SPILLMAX) nspill = SPILLMAX;
    int lane = threadIdx.x & 31;
    int nwarps = (gridDim.x * blockDim.x) >> 5;
    for (int widx = (blockIdx.x * blockDim.x + threadIdx.x) >> 5; widx < nspill; widx += nwarps) {
        int2 sp = g_spill[widx];
        const uint2* __restrict__ s2 = (PHASE == 0) ? (const uint2*)g_xh : (const uint2*)g_h;
        uint2* dst = (uint2*)((PHASE == 0) ? g_ax : g_ah);
        float dw = g_dinv[sp.x];
        float4 add = h4f(s2[(size_t)sp.y * 32 + lane]);
        float4 cur = h4f(dst[(size_t)sp.x * 32 + lane]);
        cur.x += dw * add.x; cur.y += dw * add.y;
        cur.z += dw * add.z; cur.w += dw * add.w;
        __half2 a = __floats2half2_rn(cur.x, cur.y);
        __half2 b = __floats2half2_rn(cur.z, cur.w);
        dst[(size_t)sp.x * 32 + lane] = make_uint2(*reinterpret_cast<uint32_t*>(&a),
                                                   *reinterpret_cast<uint32_t*>(&b));
    }
}

// ================= persistent HMMA GEMM: B staged once, loop row tiles =============
// A read as fp16, split exactly into bf16 hi/lo during staging.
// MODE 0: A = g_ax, B = W1; epilogue g_h(fp16) = dinv*relu(D+b1)
// MODE 1: A = g_ah, B = W2; split -> mu / logstd (+g_b2)
template <int MODE>
__global__ void __launch_bounds__(256) mma_gemm_kernel(const float* __restrict__ bias1,
                                                       float* __restrict__ out0,
                                                       float* __restrict__ out1, int n) {
    extern __shared__ __align__(16) char smem[];
    __nv_bfloat16* sAh = (__nv_bfloat16*)smem;      // 128 x KP
    __nv_bfloat16* sAl = sAh + 128 * KP;
    __nv_bfloat16* sBh = sAl + 128 * KP;
    __nv_bfloat16* sBl = sBh + 128 * KP;
    int tid = threadIdx.x;
    int lane = tid & 31, wid = tid >> 5;

    // stage B once (persistent)
    {
        const uint4* gBh = (const uint4*)((MODE == 0) ? g_w1hi : g_w2hi);
        const uint4* gBl = (const uint4*)((MODE == 0) ? g_w1lo : g_w2lo);
        for (int i = tid; i < 128 * 16; i += 256) {
            int r = i >> 4, c = i & 15;
            *(uint4*)&sBh[r * KP + c * 8] = gBh[i];
            *(uint4*)&sBl[r * KP + c * 8] = gBl[i];
        }
    }

    const uint4* gA = (const uint4*)((MODE == 0) ? g_ax : g_ah);
    const float* bias = (MODE == 0) ? bias1 : g_b2;

    int wm = wid & 3;
    int wn = wid >> 2;
    uint32_t sbase = smem_u32(smem);
    int aRow  = wm * 32 + (lane & 15);
    int aKoff = (lane >> 4) << 3;
    int bRow  = wn * 64 + ((lane >> 4) << 3) + (lane & 7);
    int bKoff = ((lane >> 3) & 1) << 3;
    int quad = lane >> 2, tq = lane & 3;

    int ntiles = (n + 127) >> 7;
    for (int tile = blockIdx.x; tile < ntiles; tile += gridDim.x) {
        int row0 = tile << 7;
        __syncthreads();   // previous iteration's ldsm of sA complete
        for (int i = tid; i < 128 * 16; i += 256) {
            int r = i >> 4, c = i & 15;
            uint4 v = (row0 + r < n) ? gA[(size_t)(row0 + r) * 16 + c] : make_uint4(0, 0, 0, 0);
            // split 8 fp16 -> bf16 hi/lo (exact: fp16 mantissa fits in hi+lo)
            const __half2* hp = (const __half2*)&v;
            uint32_t hiw[4], low[4];
#pragma unroll
            for (int q = 0; q < 4; q++) {
                float2 f = __half22float2(hp[q]);
                __nv_bfloat16 bx = __float2bfloat16_rn(f.x);
                __nv_bfloat16 by = __float2bfloat16_rn(f.y);
                __nv_bfloat162 hv = __halves2bfloat162(bx, by);
                hiw[q] = *reinterpret_cast<uint32_t*>(&hv);
                low[q] = pack_bf2(f.x - __bfloat162float(bx), f.y - __bfloat162float(by));
            }
            *(uint4*)&sAh[r * KP + c * 8] = make_uint4(hiw[0], hiw[1], hiw[2], hiw[3]);
            *(uint4*)&sAl[r * KP + c * 8] = make_uint4(low[0], low[1], low[2], low[3]);
        }
        __syncthreads();

        float d[2][8][4];
#pragma unroll
        for (int mt = 0; mt < 2; mt++)
#pragma unroll
            for (int nt = 0; nt < 8; nt++)
#pragma unroll
                for (int j = 0; j < 4; j++) d[mt][nt][j] = 0.f;

#pragma unroll
        for (int term = 0; term < 3; term++) {
            uint32_t Abase = sbase + ((term == 2) ? 1 : 0) * 128 * KP * 2;
            uint32_t Bbase = sbase + 2 * 128 * KP * 2 + ((term == 1) ? 1 : 0) * 128 * KP * 2;
#pragma unroll
            for (int ks = 0; ks < 8; ks++) {
                uint32_t a[2][4];
#pragma unroll
                for (int mt = 0; mt < 2; mt++)
                    ldsm_x4(a[mt], Abase + (uint32_t)(((aRow + mt * 16) * KP) + ks * 16 + aKoff) * 2);
                uint32_t b[8][2];
#pragma unroll
                for (int nt2 = 0; nt2 < 4; nt2++) {
                    uint32_t r4[4];
                    ldsm_x4(r4, Bbase + (uint32_t)(((bRow + nt2 * 16) * KP) + ks * 16 + bKoff) * 2);
                    b[nt2 * 2 + 0][0] = r4[0]; b[nt2 * 2 + 0][1] = r4[1];
                    b[nt2 * 2 + 1][0] = r4[2]; b[nt2 * 2 + 1][1] = r4[3];
                }
#pragma unroll
                for (int mt = 0; mt < 2; mt++)
#pragma unroll
                    for (int nt = 0; nt < 8; nt++)
                        mma16816(d[mt][nt], a[mt], b[nt]);
            }
        }

        // epilogue (registers only)
#pragma unroll
        for (int mt = 0; mt < 2; mt++) {
            int ra = row0 + wm * 32 + mt * 16 + quad;
            int rb = ra + 8;
            float da = 0.f, db = 0.f;
            if (MODE == 0) {
                if (ra < n) da = g_dinv[ra];
                if (rb < n) db = g_dinv[rb];
            }
#pragma unroll
            for (int nt = 0; nt < 8; nt++) {
                int c = wn * 64 + nt * 8 + tq * 2;
                float b0 = bias[c], b1 = bias[c + 1];
                if (MODE == 0) {
                    if (ra < n) {
                        __half2 hv = __floats2half2_rn(fmaxf(d[mt][nt][0] + b0, 0.f) * da,
                                                       fmaxf(d[mt][nt][1] + b1, 0.f) * da);
                        *(uint32_t*)&g_h[(size_t)ra * 128 + c] = *reinterpret_cast<uint32_t*>(&hv);
                    }
                    if (rb < n) {
                        __half2 hv = __floats2half2_rn(fmaxf(d[mt][nt][2] + b0, 0.f) * db,
                                                       fmaxf(d[mt][nt][3] + b1, 0.f) * db);
                        *(uint32_t*)&g_h[(size_t)rb * 128 + c] = *reinterpret_cast<uint32_t*>(&hv);
                    }
                } else {
                    float* dst = (c < 64) ? out0 : out1;
                    int cc = (c < 64) ? c : c - 64;
                    if (ra < n) {
                        float2 v = make_float2(d[mt][nt][0] + b0, d[mt][nt][1] + b1);
                        *(float2*)&dst[(size_t)ra * 64 + cc] = v;
                    }
                    if (rb < n) {
                        float2 v = make_float2(d[mt][nt][2] + b0, d[mt][nt][3] + b1);
                        *(float2*)&dst[(size_t)rb * 64 + cc] = v;
                    }
                }
            }
        }
    }
}

// ================= launch =================
#define SM_TOTAL (4 * 128 * KP * 2)

extern "C" void kernel_launch(void* const* d_in, const int* in_sizes, int n_in,
                              void* d_out, int out_size) {
    const float* x   = (const float*)d_in[0];
    const int*   ei  = (const int*)d_in[1];
    const float* W1  = (const float*)d_in[3];
    const float* b1  = (const float*)d_in[4];
    const float* Wmu = (const float*)d_in[5];
    const float* bmu = (const float*)d_in[6];
    const float* Wls = (const float*)d_in[7];
    const float* bls = (const float*)d_in[8];
    float* out = (float*)d_out;

    int n = in_sizes[0] / C;
    int e = in_sizes[1] / 2;
    const int* erow = ei;
    const int* ecol = ei + e;

    float* mu = out;
    float* ls = out + (size_t)n * 64;

    int nb_n = (n + 255) / 256;
    int nb_e = (e + 255) / 256;

    cudaFuncSetAttribute(mma_gemm_kernel<0>, cudaFuncAttributeMaxDynamicSharedMemorySize, SM_TOTAL);
    cudaFuncSetAttribute(mma_gemm_kernel<1>, cudaFuncAttributeMaxDynamicSharedMemorySize, SM_TOTAL);

    init_pack_kernel<<<nb_n + 256, 256>>>(n, nb_n, W1, Wmu, bmu, Wls, bls);
    count_scatter_kernel<<<nb_e, 256>>>(erow, ecol, e);
    dinv_scale_kernel<<<nb_n, 256>>>(x, n);

    int agg_blocks = (n + 7) / 8;

    agg_kernel<0><<<agg_blocks, 256>>>(n);
    spill_fix_kernel<0><<<128, 256>>>();
    mma_gemm_kernel<0><<<GEMM_GRID, 256, SM_TOTAL>>>(b1, nullptr, nullptr, n);
    agg_kernel<1><<<agg_blocks, 256>>>(n);
    spill_fix_kernel<1><<<128, 256>>>();
    mma_gemm_kernel<1><<<GEMM_GRID, 256, SM_TOTAL>>>(nullptr, mu, ls, n);
}